// round 1
// baseline (speedup 1.0000x reference)
#include <cuda_runtime.h>

#define HH   512
#define WW   512
#define HWSZ (HH * WW)
#define CIN  32
#define COUT 24
#define NP   8

typedef unsigned long long u64;

// ---- B300 packed-f32 helpers (sm_100+ PTX f32x2 ops; FFMA2 in SASS) ----
__device__ __forceinline__ u64 fma2_(u64 a, u64 b, u64 c) {
    u64 d; asm("fma.rn.f32x2 %0, %1, %2, %3;" : "=l"(d) : "l"(a), "l"(b), "l"(c)); return d;
}
__device__ __forceinline__ u64 add2_(u64 a, u64 b) {
    u64 d; asm("add.rn.f32x2 %0, %1, %2;" : "=l"(d) : "l"(a), "l"(b)); return d;
}
__device__ __forceinline__ u64 pack2_(float lo, float hi) {
    u64 r; asm("mov.b64 %0, {%1, %2};" : "=l"(r) : "f"(lo), "f"(hi)); return r;
}
__device__ __forceinline__ float2 unpack2_(u64 v) {
    float lo, hi; asm("mov.b64 {%0, %1}, %2;" : "=f"(lo), "=f"(hi) : "l"(v));
    return make_float2(lo, hi);
}

// Each thread: 4 x-adjacent pixels (x0 % 4 == 0), all 24 output channels in regs.
// Tap x-offsets are even, so the 5 x-taps for 4 pixels live in a contiguous
// 12-float window [x0-4, x0+7] -> 3 aligned 16B loads per (row, channel).
__global__ void __launch_bounds__(128) bilat_kernel(
    const float* __restrict__ inp, const float* __restrict__ par,
    float* __restrict__ out)
{
    const int tx = threadIdx.x & 31;
    const int ty = threadIdx.x >> 5;
    const int x0 = blockIdx.x * 128 + tx * 4;   // tile: 128 px wide
    const int y  = blockIdx.y * 4 + ty;         // 4 rows per CTA
    const int b  = blockIdx.z;

    const float* __restrict__ parb = par + b * (NP * HWSZ);
    const float* __restrict__ inpb = inp + b * (CIN * HWSZ);
    float* __restrict__ outb = out + b * (COUT * HWSZ);

    // Clamped, 16B-aligned load columns for the 12-float window
    const int xa = max(x0 - 4, 0);          // nominal v[0..3]
    const int xb = x0;                      // v[4..7]
    const int xc = min(x0 + 4, WW - 4);     // v[8..11]

    u64 acc[COUT][2];
#pragma unroll
    for (int c = 0; c < COUT; ++c) { acc[c][0] = 0ull; acc[c][1] = 0ull; }
    u64 ws0 = 0ull, ws1 = 0ull;
    const u64 M1 = 0xBF800000BF800000ull;   // (-1.0f, -1.0f)

#pragma unroll 1
    for (int dy = 0; dy < 5; ++dy) {
        const int  ny    = y + dy * 2 - 4;
        const bool rowok = ((unsigned)ny < (unsigned)HH);
        const int  nyc   = min(max(ny, 0), HH - 1);   // clamped (garbage x weight 0)
        const int  roff  = nyc * WW;

        // ---- range distances d2 for 5 x-taps x 4 pixels (packed pairs) ----
        u64 d2[5][2];
#pragma unroll
        for (int dx = 0; dx < 5; ++dx) { d2[dx][0] = 0ull; d2[dx][1] = 0ull; }

#pragma unroll
        for (int p = 0; p < NP; ++p) {
            const float* pr = parb + p * HWSZ;
            ulonglong2 cc = __ldg(reinterpret_cast<const ulonglong2*>(pr + y * WW + x0));
            ulonglong2 l0 = __ldg(reinterpret_cast<const ulonglong2*>(pr + roff + xa));
            ulonglong2 l1 = __ldg(reinterpret_cast<const ulonglong2*>(pr + roff + xb));
            ulonglong2 l2 = __ldg(reinterpret_cast<const ulonglong2*>(pr + roff + xc));
            u64 vp[6] = { l0.x, l0.y, l1.x, l1.y, l2.x, l2.y };
#pragma unroll
            for (int dx = 0; dx < 5; ++dx) {
                u64 t0 = fma2_(vp[dx],     M1, cc.x);   // center - neighbor (px 0,1)
                u64 t1 = fma2_(vp[dx + 1], M1, cc.y);   // (px 2,3)
                d2[dx][0] = fma2_(t0, t0, d2[dx][0]);
                d2[dx][1] = fma2_(t1, t1, d2[dx][1]);
            }
        }

        // ---- weights: exp(-d2), zero for OOB taps; accumulate wsum ----
        u64 w2[5][2];
#pragma unroll
        for (int dx = 0; dx < 5; ++dx) {
            float2 da = unpack2_(d2[dx][0]);
            float2 db = unpack2_(d2[dx][1]);
            float w0 = __expf(-da.x), w1 = __expf(-da.y);
            float wa = __expf(-db.x), wb = __expf(-db.y);
            const int gxb = x0 + dx * 2 - 4;  // global x of tap for px=0
            if (!rowok || (unsigned)(gxb + 0) >= (unsigned)WW) w0 = 0.0f;
            if (!rowok || (unsigned)(gxb + 1) >= (unsigned)WW) w1 = 0.0f;
            if (!rowok || (unsigned)(gxb + 2) >= (unsigned)WW) wa = 0.0f;
            if (!rowok || (unsigned)(gxb + 3) >= (unsigned)WW) wb = 0.0f;
            w2[dx][0] = pack2_(w0, w1);
            w2[dx][1] = pack2_(wa, wb);
            ws0 = add2_(ws0, w2[dx][0]);
            ws1 = add2_(ws1, w2[dx][1]);
        }

        // ---- weighted accumulation over 24 channels (weights reused from regs) ----
#pragma unroll
        for (int ch = 0; ch < COUT; ++ch) {
            const float* ir = inpb + ch * HWSZ + roff;
            ulonglong2 l0 = __ldg(reinterpret_cast<const ulonglong2*>(ir + xa));
            ulonglong2 l1 = __ldg(reinterpret_cast<const ulonglong2*>(ir + xb));
            ulonglong2 l2 = __ldg(reinterpret_cast<const ulonglong2*>(ir + xc));
            u64 vp[6] = { l0.x, l0.y, l1.x, l1.y, l2.x, l2.y };
#pragma unroll
            for (int dx = 0; dx < 5; ++dx) {
                acc[ch][0] = fma2_(w2[dx][0], vp[dx],     acc[ch][0]);
                acc[ch][1] = fma2_(w2[dx][1], vp[dx + 1], acc[ch][1]);
            }
        }
    }

    // ---- normalize and store (vectorized 16B stores) ----
    float2 s0 = unpack2_(ws0), s1 = unpack2_(ws1);
    const float r0 = 1.0f / (s0.x + 1e-8f);
    const float r1 = 1.0f / (s0.y + 1e-8f);
    const float r2 = 1.0f / (s1.x + 1e-8f);
    const float r3 = 1.0f / (s1.y + 1e-8f);

    const int obase = y * WW + x0;
#pragma unroll
    for (int ch = 0; ch < COUT; ++ch) {
        float2 a0 = unpack2_(acc[ch][0]);
        float2 a1 = unpack2_(acc[ch][1]);
        float4 o = make_float4(a0.x * r0, a0.y * r1, a1.x * r2, a1.y * r3);
        *reinterpret_cast<float4*>(outb + ch * HWSZ + obase) = o;
    }
}

extern "C" void kernel_launch(void* const* d_in, const int* in_sizes, int n_in,
                              void* d_out, int out_size)
{
    const float* inp = (const float*)d_in[0];   // (4,32,512,512) f32
    const float* par = (const float*)d_in[1];   // (4, 8,512,512) f32
    // Robustness: identify tensors by size in case of ordering surprises.
    if (n_in >= 2 && in_sizes[0] < in_sizes[1]) {
        const float* t = inp; inp = par; par = t;
    }
    float* out = (float*)d_out;                 // (4,24,512,512) f32

    dim3 grid(WW / 128, HH / 4, 4);
    dim3 block(128);
    bilat_kernel<<<grid, block>>>(inp, par, out);
}